// round 2
// baseline (speedup 1.0000x reference)
#include <cuda_runtime.h>
#include <cuda_bf16.h>

#define N 4096
#define THREADS 256
#define SPLIT 4                  /* candidate chunks */
#define PPB 4                    /* pedestrians per block */
#define NBLOCKS (N / PPB)        /* 1024 */
#define CHUNK (N / SPLIT)        /* 1024 */
#define ITERS (CHUNK / 64)       /* 16: 64 candidates per warp-iter via float4 */

typedef unsigned long long ull;

__device__ __forceinline__ void ins4(float dd, int j, float d[4], int id[4]) {
    // sorted insertion; strict < keeps earlier index first on exact ties
    if (dd < d[3]) {
        if (dd < d[2]) {
            d[3] = d[2]; id[3] = id[2];
            if (dd < d[1]) {
                d[2] = d[1]; id[2] = id[1];
                if (dd < d[0]) {
                    d[1] = d[0]; id[1] = id[0];
                    d[0] = dd; id[0] = j;
                } else { d[1] = dd; id[1] = j; }
            } else { d[2] = dd; id[2] = j; }
        } else { d[3] = dd; id[3] = j; }
    }
}

__device__ __forceinline__ ull warp_min_ull(ull k) {
    #pragma unroll
    for (int off = 16; off; off >>= 1) {
        ull o = __shfl_xor_sync(0xffffffffu, k, off);
        if (o < k) k = o;
    }
    return k;
}

__global__ __launch_bounds__(THREADS)
void nn_tag_pool_kernel(const float* __restrict__ obs1,
                        const float* __restrict__ obs2,
                        const float* __restrict__ W,
                        const float* __restrict__ b,
                        float* __restrict__ out)
{
    __shared__ ull s_keys[PPB][SPLIT][4];   // 512 B

    const int tid  = threadIdx.x;
    const int lane = tid & 31;
    const int warp = tid >> 5;
    const int pair  = warp & 1;    // which ped-pair of this block
    const int chunk = warp >> 1;   // which candidate chunk

    const int i0 = blockIdx.x * PPB + pair * 2;
    const int i1 = i0 + 1;

    const float2* __restrict__ pos2 = (const float2*)obs2;
    const float4* __restrict__ pos4 = (const float4*)obs2;

    const float2 pa = __ldg(&pos2[i0]);
    const float2 pb = __ldg(&pos2[i1]);

    const float INF = __int_as_float(0x7f800000);
    float dA[4] = {INF, INF, INF, INF};
    float dB[4] = {INF, INF, INF, INF};
    int   iA[4] = {0, 0, 0, 0};
    int   iB[4] = {0, 0, 0, 0};

    // Scan this warp's 1024-candidate chunk: one LDG.128 = 2 candidates,
    // amortized over 2 pedestrians (4 distances per load).
    const int jbase = chunk * CHUNK + lane * 2;
    #pragma unroll 4
    for (int t = 0; t < ITERS; t++) {
        const int j = jbase + t * 64;
        const float4 p = __ldg(&pos4[j >> 1]);
        {   float dx = p.x - pa.x, dy = p.y - pa.y;
            float dd = fmaf(dx, dx, fmaf(dy, dy, 1.0f));
            if (j != i0) ins4(dd, j, dA, iA); }
        {   float dx = p.z - pa.x, dy = p.w - pa.y;
            float dd = fmaf(dx, dx, fmaf(dy, dy, 1.0f));
            if (j + 1 != i0) ins4(dd, j + 1, dA, iA); }
        {   float dx = p.x - pb.x, dy = p.y - pb.y;
            float dd = fmaf(dx, dx, fmaf(dy, dy, 1.0f));
            if (j != i1) ins4(dd, j, dB, iB); }
        {   float dx = p.z - pb.x, dy = p.w - pb.y;
            float dd = fmaf(dx, dx, fmaf(dy, dy, 1.0f));
            if (j + 1 != i1) ins4(dd, j + 1, dB, iB); }
    }

    // Chunk-local top-4 (warp reduce over composite keys), stash to smem.
    #pragma unroll
    for (int r = 0; r < 4; r++) {
        ull my = (((ull)__float_as_uint(dA[0])) << 32) | (unsigned)iA[0];
        ull k = warp_min_ull(my);
        if (lane == r) s_keys[pair * 2 + 0][chunk][r] = k;
        if (my == k) {  // unique: candidate ids are distinct per lane
            dA[0] = dA[1]; iA[0] = iA[1];
            dA[1] = dA[2]; iA[1] = iA[2];
            dA[2] = dA[3]; iA[2] = iA[3];
            dA[3] = INF;
        }
    }
    #pragma unroll
    for (int r = 0; r < 4; r++) {
        ull my = (((ull)__float_as_uint(dB[0])) << 32) | (unsigned)iB[0];
        ull k = warp_min_ull(my);
        if (lane == r) s_keys[pair * 2 + 1][chunk][r] = k;
        if (my == k) {
            dB[0] = dB[1]; iB[0] = iB[1];
            dB[1] = dB[2]; iB[1] = iB[2];
            dB[2] = dB[3]; iB[2] = iB[3];
            dB[3] = INF;
        }
    }
    __syncthreads();

    // Final merge + epilogue: warp p handles pedestrian p of this block.
    if (warp < PPB) {
        const int i = blockIdx.x * PPB + warp;
        ull my = 0xFFFFFFFFFFFFFFFFull;
        if (lane < SPLIT * 4) my = s_keys[warp][lane >> 2][lane & 3];

        const int kk = lane >> 3;   // neighbor rank for this lane
        const int o  = lane & 7;    // output channel for this lane
        int nb = 0;
        #pragma unroll
        for (int r = 0; r < 4; r++) {
            ull k = warp_min_ull(my);
            if (kk == r) nb = (int)(k & 0xffffffffull);
            if (my == k) my = 0xFFFFFFFFFFFFFFFFull;
        }

        // Features for (neighbor kk, channel o); tag features fold into bias.
        const float2* __restrict__ o1 = (const float2*)obs1;
        const float2 pi = __ldg(&pos2[i]);
        const float2 pn = __ldg(&pos2[nb]);
        const float2 qi = __ldg(&o1[i]);
        const float2 qn = __ldg(&o1[nb]);
        const float px = pn.x - pi.x;
        const float py = pn.y - pi.y;
        const float vx = (pn.x - qn.x) - (pi.x - qi.x);
        const float vy = (pn.y - qn.y) - (pi.y - qi.y);

        const float w0 = __ldg(&W[o * 6 + 0]);
        const float w1 = __ldg(&W[o * 6 + 1]);
        const float w2 = __ldg(&W[o * 6 + 2]);
        const float w3 = __ldg(&W[o * 6 + 3]);
        const float w4 = __ldg(&W[o * 6 + 4]);
        const float w5 = __ldg(&W[o * 6 + 5]);

        float e = __ldg(&b[o]) + w2 + w5 + w0 * px + w1 * py + w3 * vx + w4 * vy;
        out[i * 32 + lane] = fmaxf(e, 0.0f);   // coalesced 128B store per warp
    }
}

extern "C" void kernel_launch(void* const* d_in, const int* in_sizes, int n_in,
                              void* d_out, int out_size)
{
    const float* obs1 = (const float*)d_in[0];
    const float* obs2 = (const float*)d_in[1];
    const float* W    = (const float*)d_in[2];
    const float* b    = (const float*)d_in[3];
    float* out = (float*)d_out;

    nn_tag_pool_kernel<<<NBLOCKS, THREADS>>>(obs1, obs2, W, b, out);
}

// round 3
// speedup vs baseline: 1.5156x; 1.5156x over previous
#include <cuda_runtime.h>
#include <cuda_bf16.h>

#define N 4096
#define THREADS 128
#define WARPS_PB 4
#define NBLOCKS (N / WARPS_PB)   /* 1024 */
#define ITERS (N / 64)           /* 64 iters: 2 candidates/lane/iter via float4 */

typedef unsigned long long ull;

__global__ __launch_bounds__(THREADS)
void nn_tag_pool_kernel(const float* __restrict__ obs1,
                        const float* __restrict__ obs2,
                        const float* __restrict__ W,
                        const float* __restrict__ b,
                        float* __restrict__ out)
{
    __shared__ int s_cnt[WARPS_PB];
    __shared__ ull s_buf[WARPS_PB][16];

    const int lane = threadIdx.x & 31;
    const int warp = threadIdx.x >> 5;
    const int i = blockIdx.x * WARPS_PB + warp;   // one pedestrian per warp

    const float2* __restrict__ pos2 = (const float2*)obs2;
    const float4* __restrict__ pos4 = (const float4*)obs2;
    const float2 pi = __ldg(&pos2[i]);

    const float INF = __int_as_float(0x7f800000);
    float d0 = INF, d1 = INF, d2 = INF, d3 = INF, d4 = INF;

    // ---- Phase 1: branchless distance-only scan, per-lane sorted top-5.
    // Self is included: its dd is exactly 1.0, the guaranteed global minimum
    // (dd = r^2 + 1 >= 1, equality iff identical position).
    #pragma unroll 8
    for (int t = 0; t < ITERS; t++) {
        const float4 p = __ldg(&pos4[t * 32 + lane]);
        float ax = p.x - pi.x, ay = p.y - pi.y;
        float ta = fmaf(ax, ax, fmaf(ay, ay, 1.0f));
        float bx = p.z - pi.x, by = p.w - pi.y;
        float tb = fmaf(bx, bx, fmaf(by, by, 1.0f));
        // sorted insert of ta (9 FMNMX, alu pipe, no predicates)
        float m, q;
        m = fmaxf(d0, ta); d0 = fminf(d0, ta);
        q = fmaxf(d1, m);  d1 = fminf(d1, m);  m = q;
        q = fmaxf(d2, m);  d2 = fminf(d2, m);  m = q;
        q = fmaxf(d3, m);  d3 = fminf(d3, m);  m = q;
        d4 = fminf(d4, m);
        // sorted insert of tb
        m = fmaxf(d0, tb); d0 = fminf(d0, tb);
        q = fmaxf(d1, m);  d1 = fminf(d1, m);  m = q;
        q = fmaxf(d2, m);  d2 = fminf(d2, m);  m = q;
        q = fmaxf(d3, m);  d3 = fminf(d3, m);  m = q;
        d4 = fminf(d4, m);
    }

    // ---- Phase 2: extract the 5 smallest warp-wide distances.
    // First pop is self's 1.0; the 5th pop is the 4th-neighbor distance.
    float vth = INF;
    #pragma unroll
    for (int r = 0; r < 5; r++) {
        float m = d0;
        #pragma unroll
        for (int off = 16; off; off >>= 1)
            m = fminf(m, __shfl_xor_sync(0xffffffffu, m, off));
        unsigned bal = __ballot_sync(0xffffffffu, d0 == m);
        if (lane == __ffs(bal) - 1) { d0 = d1; d1 = d2; d2 = d3; d3 = d4; d4 = INF; }
        vth = m;
    }

    if (lane == 0) s_cnt[warp] = 0;
    __syncwarp();

    // ---- Phase 3: rescan to recover indices of candidates with dd <= vth.
    // Expected matches: exactly 4 (more only on exact float ties at the boundary).
    #pragma unroll 4
    for (int t = 0; t < ITERS; t++) {
        const float4 p = __ldg(&pos4[t * 32 + lane]);
        float ax = p.x - pi.x, ay = p.y - pi.y;
        float ta = fmaf(ax, ax, fmaf(ay, ay, 1.0f));
        float bx = p.z - pi.x, by = p.w - pi.y;
        float tb = fmaf(bx, bx, fmaf(by, by, 1.0f));
        const int j0 = (t * 32 + lane) * 2;
        if (ta <= vth && j0 != i) {
            int s = atomicAdd(&s_cnt[warp], 1);
            if (s < 16)
                s_buf[warp][s] = (((ull)__float_as_uint(ta)) << 32) | (unsigned)j0;
        }
        if (tb <= vth && (j0 + 1) != i) {
            int s = atomicAdd(&s_cnt[warp], 1);
            if (s < 16)
                s_buf[warp][s] = (((ull)__float_as_uint(tb)) << 32) | (unsigned)(j0 + 1);
        }
    }
    __syncwarp();

    // ---- Phase 4: exact top-4 of recorded candidates by (dist, idx) key.
    // Composite key reproduces jax.lax.top_k's lower-index tie-break.
    int n = s_cnt[warp]; if (n > 16) n = 16;
    ull my = (lane < n) ? s_buf[warp][lane] : ~0ull;
    const int kk = lane >> 3;   // neighbor rank handled by this lane
    const int o  = lane & 7;    // output channel handled by this lane
    int nb = 0;
    #pragma unroll
    for (int r = 0; r < 4; r++) {
        ull k = my;
        #pragma unroll
        for (int off = 16; off; off >>= 1) {
            ull x = __shfl_xor_sync(0xffffffffu, k, off);
            if (x < k) k = x;
        }
        if (kk == r) nb = (int)(k & 0xffffffffull);
        if (my == k) my = ~0ull;   // keys unique (idx unique): pops exactly one
    }

    // ---- Phase 5: epilogue. Tag features (=1) fold into the bias.
    const float2* __restrict__ o1 = (const float2*)obs1;
    const float2 pn = __ldg(&pos2[nb]);
    const float2 qi = __ldg(&o1[i]);
    const float2 qn = __ldg(&o1[nb]);
    const float px = pn.x - pi.x;
    const float py = pn.y - pi.y;
    const float vx = (pn.x - qn.x) - (pi.x - qi.x);
    const float vy = (pn.y - qn.y) - (pi.y - qi.y);

    const float w0 = __ldg(&W[o * 6 + 0]);
    const float w1 = __ldg(&W[o * 6 + 1]);
    const float w2 = __ldg(&W[o * 6 + 2]);
    const float w3 = __ldg(&W[o * 6 + 3]);
    const float w4 = __ldg(&W[o * 6 + 4]);
    const float w5 = __ldg(&W[o * 6 + 5]);

    float e = __ldg(&b[o]) + w2 + w5 + w0 * px + w1 * py + w3 * vx + w4 * vy;
    out[i * 32 + lane] = fmaxf(e, 0.0f);   // coalesced 128B store per warp
}

extern "C" void kernel_launch(void* const* d_in, const int* in_sizes, int n_in,
                              void* d_out, int out_size)
{
    const float* obs1 = (const float*)d_in[0];
    const float* obs2 = (const float*)d_in[1];
    const float* W    = (const float*)d_in[2];
    const float* b    = (const float*)d_in[3];
    float* out = (float*)d_out;

    nn_tag_pool_kernel<<<NBLOCKS, THREADS>>>(obs1, obs2, W, b, out);
}

// round 4
// speedup vs baseline: 1.8932x; 1.2492x over previous
#include <cuda_runtime.h>
#include <cuda_bf16.h>

#define N 4096
#define THREADS 256
#define PPB 4                     /* pedestrians per block */
#define SPLIT 2                   /* candidate halves per pedestrian */
#define NBLOCKS (N / PPB)         /* 1024 */
#define HALF4 (N / 2 / SPLIT / 32) /* 32 float4-iters per warp */
#define BUFCAP 16

typedef unsigned long long ull;

__global__ __launch_bounds__(THREADS)
void nn_tag_pool_kernel(const float* __restrict__ obs1,
                        const float* __restrict__ obs2,
                        const float* __restrict__ W,
                        const float* __restrict__ b,
                        float* __restrict__ out)
{
    __shared__ int s_cnt[PPB];
    __shared__ int s_vth[PPB];          // positive-float bits: int order == float order
    __shared__ ull s_buf[PPB][BUFCAP];

    const int lane = threadIdx.x & 31;
    const int warp = threadIdx.x >> 5;
    const int ped  = warp >> 1;          // 0..3
    const int half = warp & 1;           // candidate half
    const int i = blockIdx.x * PPB + ped;

    if (threadIdx.x < PPB) { s_cnt[threadIdx.x] = 0; s_vth[threadIdx.x] = 0x7f800000; }
    __syncthreads();

    const float2* __restrict__ pos2 = (const float2*)obs2;
    const float4* __restrict__ pos4 = (const float4*)obs2;
    const float2 pi = __ldg(&pos2[i]);

    const float INF = __int_as_float(0x7f800000);
    float d0 = INF, d1 = INF;

    // ---- Phase 1: per-lane top-2 of this warp's 2048-candidate half.
    // Self included (dd == 1.0 exactly, the guaranteed minimum).
    const int base4 = half * (N / 2 / SPLIT) + lane;   // float4 index base
    #pragma unroll 8
    for (int t = 0; t < HALF4; t++) {
        const float4 p = __ldg(&pos4[base4 + t * 32]);
        float ax = p.x - pi.x, ay = p.y - pi.y;
        float ta = fmaf(ax, ax, fmaf(ay, ay, 1.0f));
        float bx = p.z - pi.x, by = p.w - pi.y;
        float tb = fmaf(bx, bx, fmaf(by, by, 1.0f));
        // keep 2 smallest of {d0,d1,ta,tb}: 6 FMNMX, branchless
        float lo = fminf(ta, tb), hi = fmaxf(ta, tb);
        float m0 = fmaxf(d0, lo);
        d0 = fminf(d0, lo);
        d1 = fminf(fminf(d1, hi), m0);
    }

    // ---- Phase 2: 5th-smallest of retained values (>= local true 5th >= global 5th).
    float v5 = INF;
    #pragma unroll
    for (int r = 0; r < 5; r++) {
        float m = d0;
        #pragma unroll
        for (int off = 16; off; off >>= 1)
            m = fminf(m, __shfl_xor_sync(0xffffffffu, m, off));
        unsigned bal = __ballot_sync(0xffffffffu, d0 == m);
        if (lane == __ffs(bal) - 1) { d0 = d1; d1 = INF; }
        v5 = m;
    }
    if (lane == 0) atomicMin(&s_vth[ped], __float_as_int(v5));
    __syncthreads();

    // vth = min of both halves' local 5ths: >= global 5th smallest (incl self),
    // so all true top-4 neighbors (and self) pass the filter below.
    const float vth = __int_as_float(s_vth[ped]);

    // ---- Phase 3: rescan this half; record (dist, idx) for dd <= vth.
    #pragma unroll 4
    for (int t = 0; t < HALF4; t++) {
        const float4 p = __ldg(&pos4[base4 + t * 32]);
        float ax = p.x - pi.x, ay = p.y - pi.y;
        float ta = fmaf(ax, ax, fmaf(ay, ay, 1.0f));
        float bx = p.z - pi.x, by = p.w - pi.y;
        float tb = fmaf(bx, bx, fmaf(by, by, 1.0f));
        const int j0 = (base4 + t * 32) * 2;
        if (ta <= vth) {
            int s = atomicAdd(&s_cnt[ped], 1);
            if (s < BUFCAP)
                s_buf[ped][s] = (((ull)__float_as_uint(ta)) << 32) | (unsigned)j0;
        }
        if (tb <= vth) {
            int s = atomicAdd(&s_cnt[ped], 1);
            if (s < BUFCAP)
                s_buf[ped][s] = (((ull)__float_as_uint(tb)) << 32) | (unsigned)(j0 + 1);
        }
    }
    __syncthreads();

    // ---- Phase 4 + epilogue: warps 0..3 each finish one pedestrian.
    if (warp < PPB) {
        const int ip = blockIdx.x * PPB + warp;
        int n = s_cnt[warp]; if (n > BUFCAP) n = BUFCAP;
        ull my = (lane < n) ? s_buf[warp][lane] : ~0ull;
        // exclude self by exact key: dd(self) == 1.0f bit-exactly
        const ull selfkey = (((ull)0x3f800000u) << 32) | (unsigned)ip;
        if (my == selfkey) my = ~0ull;

        const int kk = lane >> 3;   // neighbor rank for this lane
        const int o  = lane & 7;    // output channel for this lane
        int nb = 0;
        #pragma unroll
        for (int r = 0; r < 4; r++) {
            ull k = my;
            #pragma unroll
            for (int off = 16; off; off >>= 1) {
                ull x = __shfl_xor_sync(0xffffffffu, k, off);
                if (x < k) k = x;
            }
            if (kk == r) nb = (int)(k & 0xffffffffull);
            if (my == k) my = ~0ull;   // keys unique (idx in low bits)
        }

        const float2* __restrict__ o1 = (const float2*)obs1;
        const float2 pp = __ldg(&pos2[ip]);
        const float2 pn = __ldg(&pos2[nb]);
        const float2 qi = __ldg(&o1[ip]);
        const float2 qn = __ldg(&o1[nb]);
        const float px = pn.x - pp.x;
        const float py = pn.y - pp.y;
        const float vx = (pn.x - qn.x) - (pp.x - qi.x);
        const float vy = (pn.y - qn.y) - (pp.y - qi.y);

        const float w0 = __ldg(&W[o * 6 + 0]);
        const float w1 = __ldg(&W[o * 6 + 1]);
        const float w2 = __ldg(&W[o * 6 + 2]);
        const float w3 = __ldg(&W[o * 6 + 3]);
        const float w4 = __ldg(&W[o * 6 + 4]);
        const float w5 = __ldg(&W[o * 6 + 5]);

        float e = __ldg(&b[o]) + w2 + w5 + w0 * px + w1 * py + w3 * vx + w4 * vy;
        out[ip * 32 + lane] = fmaxf(e, 0.0f);   // coalesced 128B store per warp
    }
}

extern "C" void kernel_launch(void* const* d_in, const int* in_sizes, int n_in,
                              void* d_out, int out_size)
{
    const float* obs1 = (const float*)d_in[0];
    const float* obs2 = (const float*)d_in[1];
    const float* W    = (const float*)d_in[2];
    const float* b    = (const float*)d_in[3];
    float* out = (float*)d_out;

    nn_tag_pool_kernel<<<NBLOCKS, THREADS>>>(obs1, obs2, W, b, out);
}

// round 6
// speedup vs baseline: 2.0879x; 1.1028x over previous
#include <cuda_runtime.h>
#include <cuda_bf16.h>

#define N 4096
#define THREADS 256
#define PPB 4                      /* pedestrians per block */
#define NBLOCKS (N / PPB)          /* 1024 */
#define QF4 (N / 2 / 4)            /* 512 float4s per quarter-chunk */
#define ITERS (QF4 / 32)           /* 16 */
#define BUFCAP 32

typedef unsigned long long ull;
#define FULL 0xffffffffu
#define INFBITS 0x7f800000u

__device__ __forceinline__ unsigned fifth_smallest(float d0, float d1, int lane) {
    // 5th smallest of the warp's retained 64 values (>= chunk 5th >= global 5th)
    unsigned e0 = __float_as_uint(d0), e1 = __float_as_uint(d1);
    unsigned m = INFBITS;
    #pragma unroll
    for (int r = 0; r < 5; r++) {
        m = __reduce_min_sync(FULL, e0);
        unsigned bal = __ballot_sync(FULL, e0 == m);
        if (lane == __ffs(bal) - 1) { e0 = e1; e1 = INFBITS; }
    }
    return m;
}

__global__ __launch_bounds__(THREADS)
void nn_tag_pool_kernel(const float* __restrict__ obs1,
                        const float* __restrict__ obs2,
                        const float* __restrict__ W,
                        const float* __restrict__ b,
                        float* __restrict__ out)
{
    __shared__ unsigned s_cnt[PPB];
    __shared__ unsigned s_vth[PPB];     // positive-float bits: uint order == float order
    __shared__ ull s_buf[PPB][BUFCAP];

    const int lane = threadIdx.x & 31;
    const int warp = threadIdx.x >> 5;
    const int pair    = warp >> 2;       // 0..1 : which ped-pair of this block
    const int quarter = warp & 3;        // 0..3 : which candidate quarter
    const int i0 = blockIdx.x * PPB + pair * 2;
    const int i1 = i0 + 1;

    if (threadIdx.x < PPB) { s_cnt[threadIdx.x] = 0; s_vth[threadIdx.x] = INFBITS; }
    __syncthreads();

    const float2* __restrict__ pos2 = (const float2*)obs2;
    const float4* __restrict__ pos4 = (const float4*)obs2;
    const float2 pa = __ldg(&pos2[i0]);
    const float2 pb = __ldg(&pos2[i1]);

    const float INF = __int_as_float(INFBITS);
    float a0 = INF, a1 = INF;   // ped A per-lane top-2 (self included, dd==1.0 min)
    float b0 = INF, b1 = INF;   // ped B

    const int base4 = quarter * QF4 + lane;

    // ---- Phase 1: distance-only scan. One LDG.128 = 2 candidates x 2 peds.
    #pragma unroll
    for (int t = 0; t < ITERS; t++) {
        const float4 p = __ldg(&pos4[base4 + t * 32]);
        float axA = p.x - pa.x, ayA = p.y - pa.y;
        float taA = fmaf(axA, axA, fmaf(ayA, ayA, 1.0f));
        float bxA = p.z - pa.x, byA = p.w - pa.y;
        float tbA = fmaf(bxA, bxA, fmaf(byA, byA, 1.0f));
        float axB = p.x - pb.x, ayB = p.y - pb.y;
        float taB = fmaf(axB, axB, fmaf(ayB, ayB, 1.0f));
        float bxB = p.z - pb.x, byB = p.w - pb.y;
        float tbB = fmaf(bxB, bxB, fmaf(byB, byB, 1.0f));
        // branchless keep-2-smallest (6 FMNMX per ped)
        {   float lo = fminf(taA, tbA), hi = fmaxf(taA, tbA);
            float m0 = fmaxf(a0, lo);
            a0 = fminf(a0, lo);
            a1 = fminf(fminf(a1, hi), m0); }
        {   float lo = fminf(taB, tbB), hi = fmaxf(taB, tbB);
            float m0 = fmaxf(b0, lo);
            b0 = fminf(b0, lo);
            b1 = fminf(fminf(b1, hi), m0); }
    }

    // ---- Phase 2: per-chunk retained-5th; combine via atomicMin.
    // vth >= global 5th-smallest (incl. self) >= true 4th-neighbor distance,
    // so the phase-3 filter is exhaustive for top-4 + self.
    unsigned vA = fifth_smallest(a0, a1, lane);
    unsigned vB = fifth_smallest(b0, b1, lane);
    if (lane == 0) {
        atomicMin(&s_vth[pair * 2 + 0], vA);
        atomicMin(&s_vth[pair * 2 + 1], vB);
    }
    __syncthreads();
    const float vthA = __uint_as_float(s_vth[pair * 2 + 0]);
    const float vthB = __uint_as_float(s_vth[pair * 2 + 1]);

    // ---- Phase 3: rescan; record (distbits, idx) for dd <= vth (rare).
    #pragma unroll 4
    for (int t = 0; t < ITERS; t++) {
        const float4 p = __ldg(&pos4[base4 + t * 32]);
        float axA = p.x - pa.x, ayA = p.y - pa.y;
        float taA = fmaf(axA, axA, fmaf(ayA, ayA, 1.0f));
        float bxA = p.z - pa.x, byA = p.w - pa.y;
        float tbA = fmaf(bxA, bxA, fmaf(byA, byA, 1.0f));
        float axB = p.x - pb.x, ayB = p.y - pb.y;
        float taB = fmaf(axB, axB, fmaf(ayB, ayB, 1.0f));
        float bxB = p.z - pb.x, byB = p.w - pb.y;
        float tbB = fmaf(bxB, bxB, fmaf(byB, byB, 1.0f));
        const unsigned j0 = (unsigned)((base4 + t * 32) * 2);
        if (taA <= vthA) {
            unsigned s = atomicAdd(&s_cnt[pair * 2 + 0], 1u);
            if (s < BUFCAP) s_buf[pair * 2 + 0][s] = (((ull)__float_as_uint(taA)) << 32) | j0;
        }
        if (tbA <= vthA) {
            unsigned s = atomicAdd(&s_cnt[pair * 2 + 0], 1u);
            if (s < BUFCAP) s_buf[pair * 2 + 0][s] = (((ull)__float_as_uint(tbA)) << 32) | (j0 + 1);
        }
        if (taB <= vthB) {
            unsigned s = atomicAdd(&s_cnt[pair * 2 + 1], 1u);
            if (s < BUFCAP) s_buf[pair * 2 + 1][s] = (((ull)__float_as_uint(taB)) << 32) | j0;
        }
        if (tbB <= vthB) {
            unsigned s = atomicAdd(&s_cnt[pair * 2 + 1], 1u);
            if (s < BUFCAP) s_buf[pair * 2 + 1][s] = (((ull)__float_as_uint(tbB)) << 32) | (j0 + 1);
        }
    }
    __syncthreads();

    // ---- Phase 4 + epilogue: warps 0..3 each finish one pedestrian.
    if (warp < PPB) {
        const int ip = blockIdx.x * PPB + warp;
        unsigned n = s_cnt[warp]; if (n > BUFCAP) n = BUFCAP;
        unsigned db = INFBITS | 0x80000000u, ji = FULL;   // 0xffffffff = empty sentinel
        db = FULL;
        if ((unsigned)lane < n) {
            ull k = s_buf[warp][lane];
            db = (unsigned)(k >> 32);
            ji = (unsigned)k;
        }
        // exclude self: its distance is bit-exactly 1.0f
        if (db == 0x3f800000u && ji == (unsigned)ip) db = FULL;

        const int kk = lane >> 3;   // neighbor rank for this lane
        const int o  = lane & 7;    // output channel for this lane
        unsigned nb = 0;
        #pragma unroll
        for (int r = 0; r < 4; r++) {
            unsigned md = __reduce_min_sync(FULL, db);
            unsigned ci = (db == md) ? ji : FULL;
            unsigned mi = __reduce_min_sync(FULL, ci);   // lower-index tie-break
            if (kk == r) nb = mi;
            if (db == md && ji == mi) db = FULL;         // pop exactly one
        }
        nb &= (N - 1);   // memory safety (only reachable if buffer overflowed)

        const float2* __restrict__ o1 = (const float2*)obs1;
        const float2 pp = __ldg(&pos2[ip]);
        const float2 pn = __ldg(&pos2[nb]);
        const float2 qi = __ldg(&o1[ip]);
        const float2 qn = __ldg(&o1[nb]);
        const float px = pn.x - pp.x;
        const float py = pn.y - pp.y;
        const float vx = (pn.x - qn.x) - (pp.x - qi.x);
        const float vy = (pn.y - qn.y) - (pp.y - qi.y);

        const float w0 = __ldg(&W[o * 6 + 0]);
        const float w1 = __ldg(&W[o * 6 + 1]);
        const float w2 = __ldg(&W[o * 6 + 2]);
        const float w3 = __ldg(&W[o * 6 + 3]);
        const float w4 = __ldg(&W[o * 6 + 4]);
        const float w5 = __ldg(&W[o * 6 + 5]);

        float e = __ldg(&b[o]) + w2 + w5 + w0 * px + w1 * py + w3 * vx + w4 * vy;
        out[ip * 32 + lane] = fmaxf(e, 0.0f);   // coalesced 128B store per warp
    }
}

extern "C" void kernel_launch(void* const* d_in, const int* in_sizes, int n_in,
                              void* d_out, int out_size)
{
    const float* obs1 = (const float*)d_in[0];
    const float* obs2 = (const float*)d_in[1];
    const float* W    = (const float*)d_in[2];
    const float* b    = (const float*)d_in[3];
    float* out = (float*)d_out;

    nn_tag_pool_kernel<<<NBLOCKS, THREADS>>>(obs1, obs2, W, b, out);
}

// round 9
// speedup vs baseline: 2.1195x; 1.0152x over previous
#include <cuda_runtime.h>
#include <cuda_bf16.h>

#define N 4096
#define THREADS 256
#define PPB 4                      /* pedestrians per block */
#define NBLOCKS (N / PPB)          /* 1024 */
#define QF4 (N / 2 / 4)            /* 512 float4s per quarter-chunk */
#define ITERS (QF4 / 32)           /* 16 */
#define BUFCAP 32

typedef unsigned long long ull;
#define FULL 0xffffffffu
#define INFBITS 0x7f800000u

__device__ __forceinline__ ull pack2(float lo, float hi) {
    ull r;
    asm("mov.b64 %0, {%1, %2};" : "=l"(r) : "f"(lo), "f"(hi));
    return r;
}
__device__ __forceinline__ void unpack2(ull v, float& lo, float& hi) {
    asm("mov.b64 {%0, %1}, %2;" : "=f"(lo), "=f"(hi) : "l"(v));
}
__device__ __forceinline__ ull add2(ull a, ull b) {
    ull r;
    asm("add.rn.f32x2 %0, %1, %2;" : "=l"(r) : "l"(a), "l"(b));
    return r;
}
__device__ __forceinline__ ull fma2(ull a, ull b, ull c) {
    ull r;
    asm("fma.rn.f32x2 %0, %1, %2, %3;" : "=l"(r) : "l"(a), "l"(b), "l"(c));
    return r;
}

__device__ __forceinline__ unsigned fifth_smallest(float d0, float d1, int lane) {
    // 5th smallest of the warp's retained 64 values (>= chunk true 5th >= global 5th)
    unsigned e0 = __float_as_uint(d0), e1 = __float_as_uint(d1);
    unsigned m = INFBITS;
    #pragma unroll
    for (int r = 0; r < 5; r++) {
        m = __reduce_min_sync(FULL, e0);
        unsigned bal = __ballot_sync(FULL, e0 == m);
        if (lane == __ffs(bal) - 1) { e0 = e1; e1 = INFBITS; }
    }
    return m;
}

__global__ __launch_bounds__(THREADS)
void nn_tag_pool_kernel(const float* __restrict__ obs1,
                        const float* __restrict__ obs2,
                        const float* __restrict__ W,
                        const float* __restrict__ b,
                        float* __restrict__ out)
{
    __shared__ unsigned s_cnt[PPB];
    __shared__ unsigned s_vth[PPB];     // positive-float bits: uint order == float order
    __shared__ ull s_buf[PPB][BUFCAP];

    const int lane = threadIdx.x & 31;
    const int warp = threadIdx.x >> 5;
    const int pair    = warp >> 2;       // 0..1 : which ped-pair of this block
    const int quarter = warp & 3;        // 0..3 : which candidate quarter
    const int i0 = blockIdx.x * PPB + pair * 2;
    const int i1 = i0 + 1;

    if (threadIdx.x < PPB) { s_cnt[threadIdx.x] = 0; s_vth[threadIdx.x] = INFBITS; }
    __syncthreads();

    const float2* __restrict__ pos2 = (const float2*)obs2;
    const float4* __restrict__ pos4 = (const float4*)obs2;
    const float2 pa = __ldg(&pos2[i0]);
    const float2 pb = __ldg(&pos2[i1]);

    const ull ones = pack2(1.0f, 1.0f);
    const ull nax = pack2(-pa.x, -pa.x), nay = pack2(-pa.y, -pa.y);
    const ull nbx = pack2(-pb.x, -pb.x), nby = pack2(-pb.y, -pb.y);

    const float INF = __int_as_float(INFBITS);
    float a0 = INF, a1 = INF;   // ped A per-lane top-2 (self included, dd==1.0 min)
    float b0 = INF, b1 = INF;   // ped B

    const int base4 = quarter * QF4 + lane;

    // ---- Phase 1: packed distance scan, keep-2 smallest per lane per ped.
    #pragma unroll 8
    for (int t = 0; t < ITERS; t++) {
        const float4 p = __ldg(&pos4[base4 + t * 32]);
        const ull pxz = pack2(p.x, p.z);
        const ull pyw = pack2(p.y, p.w);
        // ped A: dd = dx*dx + dy*dy + 1 for both candidates, one packed stream
        {   ull dx2 = add2(pxz, nax);
            ull dy2 = add2(pyw, nay);
            ull t2  = fma2(dx2, dx2, fma2(dy2, dy2, ones));
            float ta, tb; unpack2(t2, ta, tb);
            float lo = fminf(ta, tb), hi = fmaxf(ta, tb);
            float m0 = fmaxf(a0, lo);
            a0 = fminf(a0, lo);
            a1 = fminf(fminf(a1, hi), m0); }
        // ped B
        {   ull dx2 = add2(pxz, nbx);
            ull dy2 = add2(pyw, nby);
            ull t2  = fma2(dx2, dx2, fma2(dy2, dy2, ones));
            float ta, tb; unpack2(t2, ta, tb);
            float lo = fminf(ta, tb), hi = fmaxf(ta, tb);
            float m0 = fmaxf(b0, lo);
            b0 = fminf(b0, lo);
            b1 = fminf(fminf(b1, hi), m0); }
    }

    // ---- Phase 2: per-chunk retained-5th; combine via atomicMin.
    // vth >= global 5th-smallest (incl. self), so the phase-3 filter is
    // exhaustive for the true top-4 neighbors + self. (Same retention as the
    // validated R5 configuration -> buffer counts known to fit BUFCAP.)
    unsigned vA = fifth_smallest(a0, a1, lane);
    unsigned vB = fifth_smallest(b0, b1, lane);
    if (lane == 0) {
        atomicMin(&s_vth[pair * 2 + 0], vA);
        atomicMin(&s_vth[pair * 2 + 1], vB);
    }
    __syncthreads();
    const float vthA = __uint_as_float(s_vth[pair * 2 + 0]);
    const float vthB = __uint_as_float(s_vth[pair * 2 + 1]);

    // ---- Phase 3: packed rescan; vote-gated rare append of (distbits, idx).
    #pragma unroll 4
    for (int t = 0; t < ITERS; t++) {
        const float4 p = __ldg(&pos4[base4 + t * 32]);
        const ull pxz = pack2(p.x, p.z);
        const ull pyw = pack2(p.y, p.w);
        const unsigned j0 = (unsigned)((base4 + t * 32) * 2);
        {   ull dx2 = add2(pxz, nax);
            ull dy2 = add2(pyw, nay);
            ull t2  = fma2(dx2, dx2, fma2(dy2, dy2, ones));
            float ta, tb; unpack2(t2, ta, tb);
            if (__any_sync(FULL, fminf(ta, tb) <= vthA)) {   // warp-uniform, rare
                if (ta <= vthA) {
                    unsigned s = atomicAdd(&s_cnt[pair * 2 + 0], 1u);
                    if (s < BUFCAP)
                        s_buf[pair * 2 + 0][s] = (((ull)__float_as_uint(ta)) << 32) | j0;
                }
                if (tb <= vthA) {
                    unsigned s = atomicAdd(&s_cnt[pair * 2 + 0], 1u);
                    if (s < BUFCAP)
                        s_buf[pair * 2 + 0][s] = (((ull)__float_as_uint(tb)) << 32) | (j0 + 1);
                }
            } }
        {   ull dx2 = add2(pxz, nbx);
            ull dy2 = add2(pyw, nby);
            ull t2  = fma2(dx2, dx2, fma2(dy2, dy2, ones));
            float ta, tb; unpack2(t2, ta, tb);
            if (__any_sync(FULL, fminf(ta, tb) <= vthB)) {
                if (ta <= vthB) {
                    unsigned s = atomicAdd(&s_cnt[pair * 2 + 1], 1u);
                    if (s < BUFCAP)
                        s_buf[pair * 2 + 1][s] = (((ull)__float_as_uint(ta)) << 32) | j0;
                }
                if (tb <= vthB) {
                    unsigned s = atomicAdd(&s_cnt[pair * 2 + 1], 1u);
                    if (s < BUFCAP)
                        s_buf[pair * 2 + 1][s] = (((ull)__float_as_uint(tb)) << 32) | (j0 + 1);
                }
            } }
    }
    __syncthreads();

    // ---- Phase 4 + epilogue: warps 0..3 each finish one pedestrian.
    if (warp < PPB) {
        const int ip = blockIdx.x * PPB + warp;
        unsigned n = s_cnt[warp]; if (n > BUFCAP) n = BUFCAP;
        unsigned db = FULL, ji = FULL;
        if ((unsigned)lane < n) {
            ull k = s_buf[warp][lane];
            db = (unsigned)(k >> 32);
            ji = (unsigned)k;
        }
        // exclude self: its distance is bit-exactly 1.0f
        if (db == 0x3f800000u && ji == (unsigned)ip) db = FULL;

        const int kk = lane >> 3;   // neighbor rank for this lane
        const int o  = lane & 7;    // output channel for this lane
        unsigned nb = 0;
        #pragma unroll
        for (int r = 0; r < 4; r++) {
            unsigned md = __reduce_min_sync(FULL, db);
            unsigned ci = (db == md) ? ji : FULL;
            unsigned mi = __reduce_min_sync(FULL, ci);   // lower-index tie-break
            if (kk == r) nb = mi;
            if (db == md && ji == mi) db = FULL;         // pop exactly one entry
        }
        nb &= (N - 1);   // memory safety (only reachable on overflow)

        const float2* __restrict__ o1 = (const float2*)obs1;
        const float2 pp = __ldg(&pos2[ip]);
        const float2 pn = __ldg(&pos2[nb]);
        const float2 qi = __ldg(&o1[ip]);
        const float2 qn = __ldg(&o1[nb]);
        const float px = pn.x - pp.x;
        const float py = pn.y - pp.y;
        const float vx = (pn.x - qn.x) - (pp.x - qi.x);
        const float vy = (pn.y - qn.y) - (pp.y - qi.y);

        const float w0 = __ldg(&W[o * 6 + 0]);
        const float w1 = __ldg(&W[o * 6 + 1]);
        const float w2 = __ldg(&W[o * 6 + 2]);
        const float w3 = __ldg(&W[o * 6 + 3]);
        const float w4 = __ldg(&W[o * 6 + 4]);
        const float w5 = __ldg(&W[o * 6 + 5]);

        float e = __ldg(&b[o]) + w2 + w5 + w0 * px + w1 * py + w3 * vx + w4 * vy;
        out[ip * 32 + lane] = fmaxf(e, 0.0f);   // coalesced 128B store per warp
    }
}

extern "C" void kernel_launch(void* const* d_in, const int* in_sizes, int n_in,
                              void* d_out, int out_size)
{
    const float* obs1 = (const float*)d_in[0];
    const float* obs2 = (const float*)d_in[1];
    const float* W    = (const float*)d_in[2];
    const float* b    = (const float*)d_in[3];
    float* out = (float*)d_out;

    nn_tag_pool_kernel<<<NBLOCKS, THREADS>>>(obs1, obs2, W, b, out);
}